// round 10
// baseline (speedup 1.0000x reference)
#include <cuda_runtime.h>
#include <cuda_bf16.h>
#include <cstdint>

#define BB 2
#define NN 2048
#define DD 64
#define TI 128
#define TJ 128

// ---------------- smem layout ----------------
#define OFF_XN      0                     // 128 floats
#define OFF_YN      512                   // 128 floats
#define OFF_PX      1024                  // 2048 float partials (x)
#define OFF_PY      (OFF_PX + 8192)       // 2048 float partials (y)
#define OFF_TILES   (OFF_PY + 8192)       // 17408
#define SUB_BYTES   (128 * 128)           // one bf16 subtile: 128 rows x 128B
#define OFF_AXH     (OFF_TILES + 0 * SUB_BYTES)
#define OFF_AXL     (OFF_TILES + 1 * SUB_BYTES)
#define OFF_BYH     (OFF_TILES + 2 * SUB_BYTES)
#define OFF_BYL     (OFF_TILES + 3 * SUB_BYTES)
#define SMEM_BYTES  (OFF_TILES + 4 * SUB_BYTES)   // 82944

__device__ __forceinline__ uint32_t smem_u32(const void* p) {
    uint32_t a;
    asm("{ .reg .u64 t; cvta.to.shared.u64 t, %1; cvt.u32.u64 %0, t; }" : "=r"(a) : "l"(p));
    return a;
}
#define SW128(off) ((off) ^ (((off) >> 3) & 0x70))

__device__ __forceinline__ void ldsm4(uint32_t* r, uint32_t addr) {
    asm volatile("ldmatrix.sync.aligned.m8n8.x4.shared.b16 {%0,%1,%2,%3}, [%4];"
        : "=r"(r[0]), "=r"(r[1]), "=r"(r[2]), "=r"(r[3]) : "r"(addr));
}

__device__ __forceinline__ void mma16816(float* c, const uint32_t* a,
                                         uint32_t b0, uint32_t b1) {
    asm volatile("mma.sync.aligned.m16n8k16.row.col.f32.bf16.bf16.f32 "
        "{%0,%1,%2,%3}, {%4,%5,%6,%7}, {%8,%9}, {%0,%1,%2,%3};"
        : "+f"(c[0]), "+f"(c[1]), "+f"(c[2]), "+f"(c[3])
        : "r"(a[0]), "r"(a[1]), "r"(a[2]), "r"(a[3]), "r"(b0), "r"(b1));
}

// ---------------------------------------------------------------------------
// Single kernel: 128x128 tile per CTA. bf16-split GEMM (K'=192) on HMMA.
// Norms: per-float4 partials -> smem during fill (no shfl chains), tiny
// post-barrier reduction before the mainloop.
// ---------------------------------------------------------------------------
__global__ __launch_bounds__(256, 2)
void pd_kernel(const float* __restrict__ x, const float* __restrict__ y,
               float* __restrict__ out) {
    extern __shared__ char smem[];
    uint32_t sb = smem_u32(smem);
    int tid = threadIdx.x;
    int wid = tid >> 5;
    int lane = tid & 31;
    int b = blockIdx.z;
    int i0 = blockIdx.y * TI;
    int j0 = blockIdx.x * TJ;

    float* xns_sm = (float*)(smem + OFF_XN);
    float* yns_sm = (float*)(smem + OFF_YN);
    float* px = (float*)(smem + OFF_PX);
    float* py = (float*)(smem + OFF_PY);

    // ---- fill: LDG fp32 rows -> bf16 h/l subtiles + per-float4 norm partials ----
    const float4* xg = (const float4*)(x + ((size_t)b * NN + i0) * DD);
    const float4* yg = (const float4*)(y + ((size_t)b * NN + j0) * DD);
    #pragma unroll
    for (int it = 0; it < 8; it++) {
        int idx = tid + it * 256;          // 2048 float4 = 128 rows x 16
        int row = idx >> 4;
        int k4 = (idx & 15) << 2;
        uint32_t off = SW128((uint32_t)(row * 128 + k4 * 2));

        float4 v = xg[idx];
        px[idx] = v.x * v.x + v.y * v.y + v.z * v.z + v.w * v.w;

        __nv_bfloat162 h0 = __floats2bfloat162_rn(v.x, v.y);
        __nv_bfloat162 h1 = __floats2bfloat162_rn(v.z, v.w);
        __nv_bfloat162 l0 = __floats2bfloat162_rn(v.x - __bfloat162float(h0.x),
                                                  v.y - __bfloat162float(h0.y));
        __nv_bfloat162 l1 = __floats2bfloat162_rn(v.z - __bfloat162float(h1.x),
                                                  v.w - __bfloat162float(h1.y));
        *(uint2*)(smem + OFF_AXH + off) = make_uint2(*(uint32_t*)&h0, *(uint32_t*)&h1);
        *(uint2*)(smem + OFF_AXL + off) = make_uint2(*(uint32_t*)&l0, *(uint32_t*)&l1);

        float4 w = yg[idx];
        py[idx] = w.x * w.x + w.y * w.y + w.z * w.z + w.w * w.w;

        __nv_bfloat162 g0 = __floats2bfloat162_rn(w.x, w.y);
        __nv_bfloat162 g1 = __floats2bfloat162_rn(w.z, w.w);
        __nv_bfloat162 m0 = __floats2bfloat162_rn(w.x - __bfloat162float(g0.x),
                                                  w.y - __bfloat162float(g0.y));
        __nv_bfloat162 m1 = __floats2bfloat162_rn(w.z - __bfloat162float(g1.x),
                                                  w.w - __bfloat162float(g1.y));
        *(uint2*)(smem + OFF_BYH + off) = make_uint2(*(uint32_t*)&g0, *(uint32_t*)&g1);
        *(uint2*)(smem + OFF_BYL + off) = make_uint2(*(uint32_t*)&m0, *(uint32_t*)&m1);
    }
    __syncthreads();

    // ---- norm reduction: thread t -> row t>>1, half t&1 (8 partials each) ----
    {
        int r = tid >> 1;
        int h = tid & 1;
        const float4* px4 = (const float4*)px;
        const float4* py4 = (const float4*)py;
        int base = r * 4 + h * 2;

        float4 a0 = px4[base], a1 = px4[base + 1];
        float sx = (a0.x + a0.y) + (a0.z + a0.w) + (a1.x + a1.y) + (a1.z + a1.w);
        sx += __shfl_xor_sync(0xffffffffu, sx, 1);

        float4 b0 = py4[base], b1 = py4[base + 1];
        float sy = (b0.x + b0.y) + (b0.z + b0.w) + (b1.x + b1.y) + (b1.z + b1.w);
        sy += __shfl_xor_sync(0xffffffffu, sy, 1);

        if (h == 0) {
            xns_sm[r] = sx;
            yns_sm[r] = sy;
        }
    }
    __syncthreads();

    // ---- warp tiling: warp (mw, nw) computes rows mw*32..+31, cols nw*64..+63 ----
    int mw = wid & 3;
    int nw = wid >> 2;

    uint32_t rA[2], mskA[2];
    #pragma unroll
    for (int mt = 0; mt < 2; mt++) {
        uint32_t row = mw * 32 + mt * 16 + (lane & 7) + ((lane >> 3) & 1) * 8;
        rA[mt] = row * 128;
        mskA[mt] = (rA[mt] >> 3) & 0x70;
    }
    uint32_t kA = (lane >> 4) * 16;
    uint32_t rB[4], mskB[4];
    #pragma unroll
    for (int np = 0; np < 4; np++) {
        uint32_t row = nw * 64 + np * 16 + (lane & 7) + ((lane >> 4) & 1) * 8;
        rB[np] = row * 128;
        mskB[np] = (rB[np] >> 3) & 0x70;
    }
    uint32_t kB = ((lane >> 3) & 1) * 16;

    float acc[2][8][4];
    #pragma unroll
    for (int mt = 0; mt < 2; mt++)
        #pragma unroll
        for (int nt = 0; nt < 8; nt++)
            #pragma unroll
            for (int q = 0; q < 4; q++) acc[mt][nt][q] = 0.f;

    // ---- kb-outer mainloop: phase order hides byl ldsm latency ----
    #pragma unroll
    for (int kb = 0; kb < 4; kb++) {
        uint32_t kbyte = (uint32_t)kb * 32;

        uint32_t axh[2][4], axl[2][4];
        #pragma unroll
        for (int mt = 0; mt < 2; mt++) {
            uint32_t ko = (kbyte + kA);
            ldsm4(axh[mt], sb + OFF_AXH + rA[mt] + (ko ^ mskA[mt]));
            ldsm4(axl[mt], sb + OFF_AXL + rA[mt] + (ko ^ mskA[mt]));
        }
        uint32_t byh[4][4];
        #pragma unroll
        for (int np = 0; np < 4; np++)
            ldsm4(byh[np], sb + OFF_BYH + rB[np] + ((kbyte + kB) ^ mskB[np]));

        // phase 1: xh . yh
        #pragma unroll
        for (int mt = 0; mt < 2; mt++)
            #pragma unroll
            for (int np = 0; np < 4; np++) {
                mma16816(acc[mt][2 * np],     axh[mt], byh[np][0], byh[np][1]);
                mma16816(acc[mt][2 * np + 1], axh[mt], byh[np][2], byh[np][3]);
            }

        // byl loads issued here — covered by phase-3 MMAs below
        uint32_t byl[4][4];
        #pragma unroll
        for (int np = 0; np < 4; np++)
            ldsm4(byl[np], sb + OFF_BYL + rB[np] + ((kbyte + kB) ^ mskB[np]));

        // phase 3: xl . yh (reuses byh, no new loads)
        #pragma unroll
        for (int mt = 0; mt < 2; mt++)
            #pragma unroll
            for (int np = 0; np < 4; np++) {
                mma16816(acc[mt][2 * np],     axl[mt], byh[np][0], byh[np][1]);
                mma16816(acc[mt][2 * np + 1], axl[mt], byh[np][2], byh[np][3]);
            }
        // phase 2: xh . yl
        #pragma unroll
        for (int mt = 0; mt < 2; mt++)
            #pragma unroll
            for (int np = 0; np < 4; np++) {
                mma16816(acc[mt][2 * np],     axh[mt], byl[np][0], byl[np][1]);
                mma16816(acc[mt][2 * np + 1], axh[mt], byl[np][2], byl[np][3]);
            }
    }

    // ---- epilogue: out = xn + yn - 2*dot, direct STG.64 ----
    int g = lane >> 2;
    int tq = lane & 3;

    #pragma unroll
    for (int mt = 0; mt < 2; mt++) {
        int rlo = mw * 32 + mt * 16 + g;
        float xn_lo = xns_sm[rlo];
        float xn_hi = xns_sm[rlo + 8];
        float* out_lo = out + ((size_t)(b * NN + i0 + rlo)) * NN + j0;
        float* out_hi = out_lo + (size_t)8 * NN;
        #pragma unroll
        for (int nt = 0; nt < 8; nt++) {
            int jl = nw * 64 + nt * 8 + tq * 2;
            float yn0 = yns_sm[jl], yn1 = yns_sm[jl + 1];
            float* a4 = acc[mt][nt];
            float2 v;
            v.x = fmaf(-2.f, a4[0], xn_lo + yn0);
            v.y = fmaf(-2.f, a4[1], xn_lo + yn1);
            *(float2*)(out_lo + jl) = v;
            v.x = fmaf(-2.f, a4[2], xn_hi + yn0);
            v.y = fmaf(-2.f, a4[3], xn_hi + yn1);
            *(float2*)(out_hi + jl) = v;
        }
    }
}

extern "C" void kernel_launch(void* const* d_in, const int* in_sizes, int n_in,
                              void* d_out, int out_size) {
    const float* x = (const float*)d_in[0];
    const float* y = (const float*)d_in[1];
    float* out = (float*)d_out;

    cudaFuncSetAttribute(pd_kernel, cudaFuncAttributeMaxDynamicSharedMemorySize,
                         (int)SMEM_BYTES);

    dim3 grid(NN / TJ, NN / TI, BB);
    pd_kernel<<<grid, 256, SMEM_BYTES>>>(x, y, out);
}

// round 11
// speedup vs baseline: 1.0617x; 1.0617x over previous
#include <cuda_runtime.h>
#include <cuda_bf16.h>
#include <cstdint>

#define BB 2
#define NN 2048
#define DD 64
#define TI 128
#define TJ 128

// ---------------- smem layout ----------------
#define OFF_XN      0                     // 128 floats
#define OFF_YN      512                   // 128 floats
#define OFF_PX      1024                  // 2048 float partials (x)
#define OFF_PY      (OFF_PX + 8192)       // 2048 float partials (y)
#define OFF_TILES   (OFF_PY + 8192)       // 17408
#define SUB_BYTES   (128 * 128)           // one bf16 subtile: 128 rows x 128B
#define OFF_AXH     (OFF_TILES + 0 * SUB_BYTES)
#define OFF_AXL     (OFF_TILES + 1 * SUB_BYTES)
#define OFF_BYH     (OFF_TILES + 2 * SUB_BYTES)
#define OFF_BYL     (OFF_TILES + 3 * SUB_BYTES)
#define SMEM_BYTES  (OFF_TILES + 4 * SUB_BYTES)   // 82944

__device__ __forceinline__ uint32_t smem_u32(const void* p) {
    uint32_t a;
    asm("{ .reg .u64 t; cvta.to.shared.u64 t, %1; cvt.u32.u64 %0, t; }" : "=r"(a) : "l"(p));
    return a;
}
#define SW128(off) ((off) ^ (((off) >> 3) & 0x70))

__device__ __forceinline__ void ldsm4(uint32_t* r, uint32_t addr) {
    asm volatile("ldmatrix.sync.aligned.m8n8.x4.shared.b16 {%0,%1,%2,%3}, [%4];"
        : "=r"(r[0]), "=r"(r[1]), "=r"(r[2]), "=r"(r[3]) : "r"(addr));
}

__device__ __forceinline__ void mma16816(float* c, const uint32_t* a,
                                         uint32_t b0, uint32_t b1) {
    asm volatile("mma.sync.aligned.m16n8k16.row.col.f32.bf16.bf16.f32 "
        "{%0,%1,%2,%3}, {%4,%5,%6,%7}, {%8,%9}, {%0,%1,%2,%3};"
        : "+f"(c[0]), "+f"(c[1]), "+f"(c[2]), "+f"(c[3])
        : "r"(a[0]), "r"(a[1]), "r"(a[2]), "r"(a[3]), "r"(b0), "r"(b1));
}

// ---------------------------------------------------------------------------
// One CTA computes TWO 128x128 i-tiles against a single y-panel.
// bf16-split GEMM (K'=192) on HMMA; exact fp32 norms via smem partials.
// ---------------------------------------------------------------------------
__global__ __launch_bounds__(256, 2)
void pd_kernel(const float* __restrict__ x, const float* __restrict__ y,
               float* __restrict__ out) {
    extern __shared__ char smem[];
    uint32_t sb = smem_u32(smem);
    int tid = threadIdx.x;
    int wid = tid >> 5;
    int lane = tid & 31;
    int b = blockIdx.z;
    int i0a = blockIdx.y * (2 * TI);       // first i-tile
    int j0 = blockIdx.x * TJ;

    float* xns_sm = (float*)(smem + OFF_XN);
    float* yns_sm = (float*)(smem + OFF_YN);
    float* px = (float*)(smem + OFF_PX);
    float* py = (float*)(smem + OFF_PY);

    // ---- fill tile0: x panel + y panel -> bf16 h/l subtiles + norm partials ----
    const float4* xg = (const float4*)(x + ((size_t)b * NN + i0a) * DD);
    const float4* yg = (const float4*)(y + ((size_t)b * NN + j0) * DD);
    #pragma unroll
    for (int it = 0; it < 8; it++) {
        int idx = tid + it * 256;          // 2048 float4 = 128 rows x 16
        int row = idx >> 4;
        int k4 = (idx & 15) << 2;
        uint32_t off = SW128((uint32_t)(row * 128 + k4 * 2));

        float4 v = xg[idx];
        px[idx] = v.x * v.x + v.y * v.y + v.z * v.z + v.w * v.w;

        __nv_bfloat162 h0 = __floats2bfloat162_rn(v.x, v.y);
        __nv_bfloat162 h1 = __floats2bfloat162_rn(v.z, v.w);
        __nv_bfloat162 l0 = __floats2bfloat162_rn(v.x - __bfloat162float(h0.x),
                                                  v.y - __bfloat162float(h0.y));
        __nv_bfloat162 l1 = __floats2bfloat162_rn(v.z - __bfloat162float(h1.x),
                                                  v.w - __bfloat162float(h1.y));
        *(uint2*)(smem + OFF_AXH + off) = make_uint2(*(uint32_t*)&h0, *(uint32_t*)&h1);
        *(uint2*)(smem + OFF_AXL + off) = make_uint2(*(uint32_t*)&l0, *(uint32_t*)&l1);

        float4 w = yg[idx];
        py[idx] = w.x * w.x + w.y * w.y + w.z * w.z + w.w * w.w;

        __nv_bfloat162 g0 = __floats2bfloat162_rn(w.x, w.y);
        __nv_bfloat162 g1 = __floats2bfloat162_rn(w.z, w.w);
        __nv_bfloat162 m0 = __floats2bfloat162_rn(w.x - __bfloat162float(g0.x),
                                                  w.y - __bfloat162float(g0.y));
        __nv_bfloat162 m1 = __floats2bfloat162_rn(w.z - __bfloat162float(g1.x),
                                                  w.w - __bfloat162float(g1.y));
        *(uint2*)(smem + OFF_BYH + off) = make_uint2(*(uint32_t*)&g0, *(uint32_t*)&g1);
        *(uint2*)(smem + OFF_BYL + off) = make_uint2(*(uint32_t*)&m0, *(uint32_t*)&m1);
    }

    // prefetch second x panel (32KB = 256 lines, one per thread) into L2
    {
        const char* x1p = (const char*)(x + ((size_t)b * NN + i0a + TI) * DD);
        asm volatile("prefetch.global.L2 [%0];" :: "l"(x1p + (size_t)tid * 128));
    }
    __syncthreads();

    // ---- norm reduction (x and y): thread t -> row t>>1, half t&1 ----
    {
        int r = tid >> 1;
        int h = tid & 1;
        const float4* px4 = (const float4*)px;
        const float4* py4 = (const float4*)py;
        int base = r * 4 + h * 2;

        float4 a0 = px4[base], a1 = px4[base + 1];
        float sx = (a0.x + a0.y) + (a0.z + a0.w) + (a1.x + a1.y) + (a1.z + a1.w);
        sx += __shfl_xor_sync(0xffffffffu, sx, 1);

        float4 b0 = py4[base], b1 = py4[base + 1];
        float sy = (b0.x + b0.y) + (b0.z + b0.w) + (b1.x + b1.y) + (b1.z + b1.w);
        sy += __shfl_xor_sync(0xffffffffu, sy, 1);

        if (h == 0) {
            xns_sm[r] = sx;
            yns_sm[r] = sy;
        }
    }
    __syncthreads();

    // ---- warp tiling + lane-constant ldsm addressing (loop-invariant) ----
    int mw = wid & 3;
    int nw = wid >> 2;

    uint32_t rA[2], mskA[2];
    #pragma unroll
    for (int mt = 0; mt < 2; mt++) {
        uint32_t row = mw * 32 + mt * 16 + (lane & 7) + ((lane >> 3) & 1) * 8;
        rA[mt] = row * 128;
        mskA[mt] = (rA[mt] >> 3) & 0x70;
    }
    uint32_t kA = (lane >> 4) * 16;
    uint32_t rB[4], mskB[4];
    #pragma unroll
    for (int np = 0; np < 4; np++) {
        uint32_t row = nw * 64 + np * 16 + (lane & 7) + ((lane >> 4) & 1) * 8;
        rB[np] = row * 128;
        mskB[np] = (rB[np] >> 3) & 0x70;
    }
    uint32_t kB = ((lane >> 3) & 1) * 16;

    int g = lane >> 2;
    int tq = lane & 3;

    // ================= two i-tiles against the resident y panel =================
    #pragma unroll
    for (int t = 0; t < 2; t++) {
        int i0 = i0a + t * TI;

        if (t == 1) {
            // all warps done with ldsm-t0 (tiles) and epilogue-t0 (xns reads)
            __syncthreads();

            // refill x panel from the second i-tile (L2-resident via prefetch)
            const float4* xg1 = (const float4*)(x + ((size_t)b * NN + i0) * DD);
            #pragma unroll
            for (int it = 0; it < 8; it++) {
                int idx = tid + it * 256;
                int row = idx >> 4;
                int k4 = (idx & 15) << 2;
                uint32_t off = SW128((uint32_t)(row * 128 + k4 * 2));

                float4 v = xg1[idx];
                px[idx] = v.x * v.x + v.y * v.y + v.z * v.z + v.w * v.w;

                __nv_bfloat162 h0 = __floats2bfloat162_rn(v.x, v.y);
                __nv_bfloat162 h1 = __floats2bfloat162_rn(v.z, v.w);
                __nv_bfloat162 l0 = __floats2bfloat162_rn(v.x - __bfloat162float(h0.x),
                                                          v.y - __bfloat162float(h0.y));
                __nv_bfloat162 l1 = __floats2bfloat162_rn(v.z - __bfloat162float(h1.x),
                                                          v.w - __bfloat162float(h1.y));
                *(uint2*)(smem + OFF_AXH + off) = make_uint2(*(uint32_t*)&h0, *(uint32_t*)&h1);
                *(uint2*)(smem + OFF_AXL + off) = make_uint2(*(uint32_t*)&l0, *(uint32_t*)&l1);
            }
            __syncthreads();

            // reduce x norms only
            {
                int r = tid >> 1;
                int h = tid & 1;
                const float4* px4 = (const float4*)px;
                int base = r * 4 + h * 2;
                float4 a0 = px4[base], a1 = px4[base + 1];
                float sx = (a0.x + a0.y) + (a0.z + a0.w) + (a1.x + a1.y) + (a1.z + a1.w);
                sx += __shfl_xor_sync(0xffffffffu, sx, 1);
                if (h == 0) xns_sm[r] = sx;
            }
            __syncthreads();
        }

        float acc[2][8][4];
        #pragma unroll
        for (int mt = 0; mt < 2; mt++)
            #pragma unroll
            for (int nt = 0; nt < 8; nt++)
                #pragma unroll
                for (int q = 0; q < 4; q++) acc[mt][nt][q] = 0.f;

        // ---- kb-outer mainloop: phase order hides byl ldsm latency ----
        #pragma unroll
        for (int kb = 0; kb < 4; kb++) {
            uint32_t kbyte = (uint32_t)kb * 32;

            uint32_t axh[2][4], axl[2][4];
            #pragma unroll
            for (int mt = 0; mt < 2; mt++) {
                uint32_t ko = (kbyte + kA);
                ldsm4(axh[mt], sb + OFF_AXH + rA[mt] + (ko ^ mskA[mt]));
                ldsm4(axl[mt], sb + OFF_AXL + rA[mt] + (ko ^ mskA[mt]));
            }
            uint32_t byh[4][4];
            #pragma unroll
            for (int np = 0; np < 4; np++)
                ldsm4(byh[np], sb + OFF_BYH + rB[np] + ((kbyte + kB) ^ mskB[np]));

            // phase 1: xh . yh
            #pragma unroll
            for (int mt = 0; mt < 2; mt++)
                #pragma unroll
                for (int np = 0; np < 4; np++) {
                    mma16816(acc[mt][2 * np],     axh[mt], byh[np][0], byh[np][1]);
                    mma16816(acc[mt][2 * np + 1], axh[mt], byh[np][2], byh[np][3]);
                }

            // byl loads issued here — covered by phase-3 MMAs below
            uint32_t byl[4][4];
            #pragma unroll
            for (int np = 0; np < 4; np++)
                ldsm4(byl[np], sb + OFF_BYL + rB[np] + ((kbyte + kB) ^ mskB[np]));

            // phase 3: xl . yh (reuses byh, no new loads)
            #pragma unroll
            for (int mt = 0; mt < 2; mt++)
                #pragma unroll
                for (int np = 0; np < 4; np++) {
                    mma16816(acc[mt][2 * np],     axl[mt], byh[np][0], byh[np][1]);
                    mma16816(acc[mt][2 * np + 1], axl[mt], byh[np][2], byh[np][3]);
                }
            // phase 2: xh . yl
            #pragma unroll
            for (int mt = 0; mt < 2; mt++)
                #pragma unroll
                for (int np = 0; np < 4; np++) {
                    mma16816(acc[mt][2 * np],     axh[mt], byl[np][0], byl[np][1]);
                    mma16816(acc[mt][2 * np + 1], axh[mt], byl[np][2], byl[np][3]);
                }
        }

        // ---- epilogue: out = xn + yn - 2*dot, direct STG.64 ----
        #pragma unroll
        for (int mt = 0; mt < 2; mt++) {
            int rlo = mw * 32 + mt * 16 + g;
            float xn_lo = xns_sm[rlo];
            float xn_hi = xns_sm[rlo + 8];
            float* out_lo = out + ((size_t)(b * NN + i0 + rlo)) * NN + j0;
            float* out_hi = out_lo + (size_t)8 * NN;
            #pragma unroll
            for (int nt = 0; nt < 8; nt++) {
                int jl = nw * 64 + nt * 8 + tq * 2;
                float yn0 = yns_sm[jl], yn1 = yns_sm[jl + 1];
                float* a4 = acc[mt][nt];
                float2 v;
                v.x = fmaf(-2.f, a4[0], xn_lo + yn0);
                v.y = fmaf(-2.f, a4[1], xn_lo + yn1);
                *(float2*)(out_lo + jl) = v;
                v.x = fmaf(-2.f, a4[2], xn_hi + yn0);
                v.y = fmaf(-2.f, a4[3], xn_hi + yn1);
                *(float2*)(out_hi + jl) = v;
            }
        }
    }
}

extern "C" void kernel_launch(void* const* d_in, const int* in_sizes, int n_in,
                              void* d_out, int out_size) {
    const float* x = (const float*)d_in[0];
    const float* y = (const float*)d_in[1];
    float* out = (float*)d_out;

    cudaFuncSetAttribute(pd_kernel, cudaFuncAttributeMaxDynamicSharedMemorySize,
                         (int)SMEM_BYTES);

    dim3 grid(NN / TJ, NN / (2 * TI), BB);
    pd_kernel<<<grid, 256, SMEM_BYTES>>>(x, y, out);
}

// round 12
// speedup vs baseline: 1.3524x; 1.2739x over previous
#include <cuda_runtime.h>
#include <cuda_fp16.h>
#include <cstdint>

#define BB 2
#define NN 2048
#define DD 64
#define TI 128
#define TJ 128

// ---------------- smem layout ----------------
#define OFF_XN      0                     // 128 floats
#define OFF_YN      512                   // 128 floats
#define OFF_PX      1024                  // 2048 float partials (x)
#define OFF_PY      (OFF_PX + 8192)       // 2048 float partials (y)
#define OFF_TILES   (OFF_PY + 8192)       // 17408
#define SUB_BYTES   (128 * 128)           // fp16 subtile: 128 rows x 128B (64 halves)
#define OFF_AXH     (OFF_TILES + 0 * SUB_BYTES)
#define OFF_BYH     (OFF_TILES + 1 * SUB_BYTES)
#define SMEM_BYTES  (OFF_TILES + 2 * SUB_BYTES)   // 50176

__device__ __forceinline__ uint32_t smem_u32(const void* p) {
    uint32_t a;
    asm("{ .reg .u64 t; cvta.to.shared.u64 t, %1; cvt.u32.u64 %0, t; }" : "=r"(a) : "l"(p));
    return a;
}
#define SW128(off) ((off) ^ (((off) >> 3) & 0x70))

__device__ __forceinline__ void ldsm4(uint32_t* r, uint32_t addr) {
    asm volatile("ldmatrix.sync.aligned.m8n8.x4.shared.b16 {%0,%1,%2,%3}, [%4];"
        : "=r"(r[0]), "=r"(r[1]), "=r"(r[2]), "=r"(r[3]) : "r"(addr));
}

__device__ __forceinline__ void mma16816(float* c, const uint32_t* a,
                                         uint32_t b0, uint32_t b1) {
    asm volatile("mma.sync.aligned.m16n8k16.row.col.f32.f16.f16.f32 "
        "{%0,%1,%2,%3}, {%4,%5,%6,%7}, {%8,%9}, {%0,%1,%2,%3};"
        : "+f"(c[0]), "+f"(c[1]), "+f"(c[2]), "+f"(c[3])
        : "r"(a[0]), "r"(a[1]), "r"(a[2]), "r"(a[3]), "r"(b0), "r"(b1));
}

// y-row permutation: logical j -> physical row p, so thread's 4 acc values
// cover 4 consecutive j (enables STG.128 epilogue).
// j = q*16 + w*4 + h*2 + l  ->  p = q*16 + h*8 + w*2 + l
__device__ __forceinline__ int permute_row(int j) {
    return (j & ~15) | ((j & 2) << 2) | ((j & 12) >> 1) | (j & 1);
}

// ---------------------------------------------------------------------------
// Single kernel: 128x128 tile per CTA. fp16 single-pass GEMM on HMMA,
// exact fp32 norms; dist = xn + yn - 2*(xh . yh).
// ---------------------------------------------------------------------------
__global__ __launch_bounds__(256, 2)
void pd_kernel(const float* __restrict__ x, const float* __restrict__ y,
               float* __restrict__ out) {
    extern __shared__ char smem[];
    uint32_t sb = smem_u32(smem);
    int tid = threadIdx.x;
    int wid = tid >> 5;
    int lane = tid & 31;
    int b = blockIdx.z;
    int i0 = blockIdx.y * TI;
    int j0 = blockIdx.x * TJ;

    float* xns_sm = (float*)(smem + OFF_XN);
    float* yns_sm = (float*)(smem + OFF_YN);
    float* px = (float*)(smem + OFF_PX);
    float* py = (float*)(smem + OFF_PY);

    // ---- fill: LDG fp32 rows -> fp16 subtiles + per-float4 norm partials ----
    const float4* xg = (const float4*)(x + ((size_t)b * NN + i0) * DD);
    const float4* yg = (const float4*)(y + ((size_t)b * NN + j0) * DD);
    #pragma unroll
    for (int it = 0; it < 8; it++) {
        int idx = tid + it * 256;          // 2048 float4 = 128 rows x 16
        int row = idx >> 4;
        int k4 = (idx & 15) << 2;

        float4 v = xg[idx];
        px[idx] = v.x * v.x + v.y * v.y + v.z * v.z + v.w * v.w;
        __half2 h0 = __float22half2_rn(make_float2(v.x, v.y));
        __half2 h1 = __float22half2_rn(make_float2(v.z, v.w));
        uint32_t offx = SW128((uint32_t)(row * 128 + k4 * 2));
        *(uint2*)(smem + OFF_AXH + offx) = make_uint2(*(uint32_t*)&h0, *(uint32_t*)&h1);

        float4 w = yg[idx];
        py[idx] = w.x * w.x + w.y * w.y + w.z * w.z + w.w * w.w;
        __half2 g0 = __float22half2_rn(make_float2(w.x, w.y));
        __half2 g1 = __float22half2_rn(make_float2(w.z, w.w));
        int prow = permute_row(row);
        uint32_t offy = SW128((uint32_t)(prow * 128 + k4 * 2));
        *(uint2*)(smem + OFF_BYH + offy) = make_uint2(*(uint32_t*)&g0, *(uint32_t*)&g1);
    }
    __syncthreads();

    // ---- norm reduction: thread t -> row t>>1, half t&1 (8 partials each) ----
    {
        int r = tid >> 1;
        int h = tid & 1;
        const float4* px4 = (const float4*)px;
        const float4* py4 = (const float4*)py;
        int base = r * 4 + h * 2;

        float4 a0 = px4[base], a1 = px4[base + 1];
        float sx = (a0.x + a0.y) + (a0.z + a0.w) + (a1.x + a1.y) + (a1.z + a1.w);
        sx += __shfl_xor_sync(0xffffffffu, sx, 1);

        float4 b0 = py4[base], b1 = py4[base + 1];
        float sy = (b0.x + b0.y) + (b0.z + b0.w) + (b1.x + b1.y) + (b1.z + b1.w);
        sy += __shfl_xor_sync(0xffffffffu, sy, 1);

        if (h == 0) {
            xns_sm[r] = sx;
            yns_sm[r] = sy;
        }
    }
    __syncthreads();

    // ---- warp tiling: warp (mw, nw) -> rows mw*32..+31, cols nw*64..+63 ----
    int mw = wid & 3;
    int nw = wid >> 2;

    uint32_t rA[2], mskA[2];
    #pragma unroll
    for (int mt = 0; mt < 2; mt++) {
        uint32_t row = mw * 32 + mt * 16 + (lane & 7) + ((lane >> 3) & 1) * 8;
        rA[mt] = row * 128;
        mskA[mt] = (rA[mt] >> 3) & 0x70;
    }
    uint32_t kA = (lane >> 4) * 16;
    uint32_t rB[4], mskB[4];
    #pragma unroll
    for (int np = 0; np < 4; np++) {
        uint32_t row = nw * 64 + np * 16 + (lane & 7) + ((lane >> 4) & 1) * 8;
        rB[np] = row * 128;
        mskB[np] = (rB[np] >> 3) & 0x70;
    }
    uint32_t kB = ((lane >> 3) & 1) * 16;

    float acc[2][8][4];
    #pragma unroll
    for (int mt = 0; mt < 2; mt++)
        #pragma unroll
        for (int nt = 0; nt < 8; nt++)
            #pragma unroll
            for (int q = 0; q < 4; q++) acc[mt][nt][q] = 0.f;

    // ---- mainloop: 4 kb panels, double-buffered fragments (prefetch kb+1) ----
    uint32_t af[2][2][4], bf[2][4][4];
    #pragma unroll
    for (int mt = 0; mt < 2; mt++)
        ldsm4(af[0][mt], sb + OFF_AXH + rA[mt] + (kA ^ mskA[mt]));
    #pragma unroll
    for (int np = 0; np < 4; np++)
        ldsm4(bf[0][np], sb + OFF_BYH + rB[np] + (kB ^ mskB[np]));

    #pragma unroll
    for (int kb = 0; kb < 4; kb++) {
        int cur = kb & 1, nxt = cur ^ 1;
        if (kb < 3) {
            uint32_t kbyte = (uint32_t)(kb + 1) * 32;
            #pragma unroll
            for (int mt = 0; mt < 2; mt++)
                ldsm4(af[nxt][mt], sb + OFF_AXH + rA[mt] + ((kbyte + kA) ^ mskA[mt]));
            #pragma unroll
            for (int np = 0; np < 4; np++)
                ldsm4(bf[nxt][np], sb + OFF_BYH + rB[np] + ((kbyte + kB) ^ mskB[np]));
        }
        #pragma unroll
        for (int mt = 0; mt < 2; mt++)
            #pragma unroll
            for (int np = 0; np < 4; np++) {
                mma16816(acc[mt][2 * np],     af[cur][mt], bf[cur][np][0], bf[cur][np][1]);
                mma16816(acc[mt][2 * np + 1], af[cur][mt], bf[cur][np][2], bf[cur][np][3]);
            }
    }

    // ---- epilogue: out = xn + yn - 2*dot; permuted j -> STG.128 ----
    int g = lane >> 2;
    int tq = lane & 3;

    #pragma unroll
    for (int mt = 0; mt < 2; mt++) {
        int rlo = mw * 32 + mt * 16 + g;
        float xn_lo = xns_sm[rlo];
        float xn_hi = xns_sm[rlo + 8];
        float* out_lo = out + ((size_t)(b * NN + i0 + rlo)) * NN + j0;
        float* out_hi = out_lo + (size_t)8 * NN;
        #pragma unroll
        for (int q = 0; q < 4; q++) {
            int jl = nw * 64 + q * 16 + tq * 4;   // 4 consecutive logical j
            float4 yn = *(const float4*)(yns_sm + jl);
            float* aA = acc[mt][2 * q];       // physical block h=0 -> j+0, j+1
            float* aB = acc[mt][2 * q + 1];   // physical block h=1 -> j+2, j+3
            float4 v;
            v.x = fmaf(-2.f, aA[0], xn_lo + yn.x);
            v.y = fmaf(-2.f, aA[1], xn_lo + yn.y);
            v.z = fmaf(-2.f, aB[0], xn_lo + yn.z);
            v.w = fmaf(-2.f, aB[1], xn_lo + yn.w);
            *(float4*)(out_lo + jl) = v;
            v.x = fmaf(-2.f, aA[2], xn_hi + yn.x);
            v.y = fmaf(-2.f, aA[3], xn_hi + yn.y);
            v.z = fmaf(-2.f, aB[2], xn_hi + yn.z);
            v.w = fmaf(-2.f, aB[3], xn_hi + yn.w);
            *(float4*)(out_hi + jl) = v;
        }
    }
}

extern "C" void kernel_launch(void* const* d_in, const int* in_sizes, int n_in,
                              void* d_out, int out_size) {
    const float* x = (const float*)d_in[0];
    const float* y = (const float*)d_in[1];
    float* out = (float*)d_out;

    cudaFuncSetAttribute(pd_kernel, cudaFuncAttributeMaxDynamicSharedMemorySize,
                         (int)SMEM_BYTES);

    dim3 grid(NN / TJ, NN / TI, BB);
    pd_kernel<<<grid, 256, SMEM_BYTES>>>(x, y, out);
}